// round 15
// baseline (speedup 1.0000x reference)
#include <cuda_runtime.h>
#include <cstdint>

// RadialAEVComputer: GR[b,i,s,p] = sum_j exp(-16*(d_bij - shf_p)^2) * fc(d_bij) * [spec_bj == s+1]
// B=64, N=256, S=4, P=16, shf_p = 0.9 + 0.26875*p, RC=5.2
//
// R15: TWO warps per row, each owning 128 neighbors. Per-warp: batched-ballot
//      compaction into a private smem list, lane-pair p-split accumulation
//      (odd-from-even Gaussians, 5 ex2/neighbor), private transpose reduction.
//      Warp pair combines via smem (+1 __syncthreads). Sentinel d = RC.
//      Block = 4 warps = 2 rows; grid = 8192.

#define FULL 0xffffffffu

__device__ __forceinline__ unsigned long long pack2(float lo, float hi) {
    unsigned long long r;
    asm("mov.b64 %0, {%1, %2};" : "=l"(r) : "f"(lo), "f"(hi));
    return r;
}
__device__ __forceinline__ void fma2_acc(unsigned long long& d,
                                         unsigned long long a,
                                         unsigned long long b) {
    asm("fma.rn.f32x2 %0, %1, %2, %0;" : "+l"(d) : "l"(a), "l"(b));
}
__device__ __forceinline__ unsigned long long mul2(unsigned long long a,
                                                   unsigned long long b) {
    unsigned long long r;
    asm("mul.rn.f32x2 %0, %1, %2;" : "=l"(r) : "l"(a), "l"(b));
    return r;
}
__device__ __forceinline__ unsigned long long add2(unsigned long long a,
                                                   unsigned long long b) {
    unsigned long long r;
    asm("add.rn.f32x2 %0, %1, %2;" : "=l"(r) : "l"(a), "l"(b));
    return r;
}
__device__ __forceinline__ float ex2f(float a) {
    float t;
    asm("ex2.approx.ftz.f32 %0, %1;" : "=f"(t) : "f"(a));
    return t;
}

// delta = 0.26875, NL = -16*log2(e) = -23.0831207
//   R0 arg:  NL*delta*(delta - 2*dh) = 12.4071774*dh - 1.6672145
//   CR = 9.8282033e-3;  CR^2 = 9.6593541e-5;  CR^3 = 9.4934069e-7

template <bool FIRST>
__device__ __forceinline__ void do_chunk(unsigned long long (&acc2)[16],
                                         const float* __restrict__ sl,
                                         int base, int lane, float sbase)
{
    const float NL    = -23.0831207f;
    const float PI_RC = 0.60415244f;

    // lanes 2k, 2k+1 read the same 8-byte pair: one LDS.64, smem broadcast
    const float2 e = *reinterpret_cast<const float2*>(&sl[base + (lane & ~1)]);
    const unsigned bits0 = __float_as_uint(e.x);
    const unsigned bits1 = __float_as_uint(e.y);
    const float d0 = e.x, d1 = e.y;
    const int c0 = bits0 & 3;
    const int c1 = bits1 & 3;

    const float ws0 = fmaf(0.5f, __cosf(d0 * PI_RC), 0.5f);
    const float ws1 = fmaf(0.5f, __cosf(d1 * PI_RC), 0.5f);

    {   // neighbor 0
        const float dh = d0 - sbase;
        const float t  = dh * NL;
        const float A  = dh * t;
        const float Bv = -2.0f * t;
        const float R0 = ex2f(fmaf(dh, 12.4071774f, -1.6672145f));
        const float R1 = R0 * 9.8282033e-3f;
        const float R2 = R0 * 9.6593541e-5f;
        const float R3 = R0 * 9.4934069e-7f;
        const unsigned long long wwp = pack2(ws0, ws0);
        const unsigned long long ww0 = (c0 == 0) ? wwp : 0ull;
        const unsigned long long ww1 = (c0 == 1) ? wwp : 0ull;
        const unsigned long long ww2 = (c0 == 2) ? wwp : 0ull;
        const unsigned long long ww3 = (c0 == 3) ? wwp : 0ull;
#pragma unroll
        for (int u = 0; u < 4; ++u) {
            const float q  = 0.26875f * (float)(2 * u);
            const float g  = ex2f(fmaf(Bv, q, A) + NL * q * q);
            const float Ru = (u == 0) ? R0 : (u == 1) ? R1 : (u == 2) ? R2 : R3;
            const unsigned long long tt = pack2(g, g * Ru);
            if (FIRST) {
                acc2[u]      = mul2(tt, ww0);
                acc2[4 + u]  = mul2(tt, ww1);
                acc2[8 + u]  = mul2(tt, ww2);
                acc2[12 + u] = mul2(tt, ww3);
            } else {
                fma2_acc(acc2[u],      tt, ww0);
                fma2_acc(acc2[4 + u],  tt, ww1);
                fma2_acc(acc2[8 + u],  tt, ww2);
                fma2_acc(acc2[12 + u], tt, ww3);
            }
        }
    }
    {   // neighbor 1
        const float dh = d1 - sbase;
        const float t  = dh * NL;
        const float A  = dh * t;
        const float Bv = -2.0f * t;
        const float R0 = ex2f(fmaf(dh, 12.4071774f, -1.6672145f));
        const float R1 = R0 * 9.8282033e-3f;
        const float R2 = R0 * 9.6593541e-5f;
        const float R3 = R0 * 9.4934069e-7f;
        const unsigned long long wwp = pack2(ws1, ws1);
        const unsigned long long ww0 = (c1 == 0) ? wwp : 0ull;
        const unsigned long long ww1 = (c1 == 1) ? wwp : 0ull;
        const unsigned long long ww2 = (c1 == 2) ? wwp : 0ull;
        const unsigned long long ww3 = (c1 == 3) ? wwp : 0ull;
#pragma unroll
        for (int u = 0; u < 4; ++u) {
            const float q  = 0.26875f * (float)(2 * u);
            const float g  = ex2f(fmaf(Bv, q, A) + NL * q * q);
            const float Ru = (u == 0) ? R0 : (u == 1) ? R1 : (u == 2) ? R2 : R3;
            const unsigned long long tt = pack2(g, g * Ru);
            fma2_acc(acc2[u],      tt, ww0);
            fma2_acc(acc2[4 + u],  tt, ww1);
            fma2_acc(acc2[8 + u],  tt, ww2);
            fma2_acc(acc2[12 + u], tt, ww3);
        }
    }
}

__global__ __launch_bounds__(128, 8)
void radial_aev_kernel(const float* __restrict__ dmat,
                       const int*   __restrict__ spec,
                       float*       __restrict__ out,
                       int N)
{
    __shared__ float slist[4][128];                    // per-warp half-row list
    __shared__ unsigned long long trb[4][32][17];      // transpose buffers
    __shared__ unsigned long long psum[4][32];         // per-warp lane sums

    const int lane = threadIdx.x & 31;
    const int wid  = threadIdx.x >> 5;                 // 0..3
    const int pr   = wid >> 1;                         // row pair index in block
    const int hw   = wid & 1;                          // which half of the row
    const int row  = blockIdx.x * 2 + pr;              // b*N + i
    const int b    = row >> 8;                         // N == 256

    const float RC = 5.2f;
    const unsigned lmlt = (1u << lane) - 1u;

    // ---- Pass 1: this warp owns neighbors [hw*128, hw*128+128) ----
    const float4* __restrict__ drow4 = (const float4*)(dmat + (size_t)row * N) + hw * 32;
    const int4*   __restrict__ srow4 = (const int4*)(spec + b * N) + hw * 32;

    const float4 dv = drow4[lane];
    const int4   sv = srow4[lane];

    const float dk[4] = { dv.x, dv.y, dv.z, dv.w };
    const int   sk[4] = { sv.x, sv.y, sv.z, sv.w };

    unsigned mk[4];
#pragma unroll
    for (int k = 0; k < 4; ++k)                        // independent ballots
        mk[k] = __ballot_sync(FULL, (dk[k] < RC) && (dk[k] != 0.0f));

    unsigned cnt = 0;
#pragma unroll
    for (int k = 0; k < 4; ++k) {
        if ((mk[k] >> lane) & 1u) {
            const unsigned bits = (__float_as_uint(dk[k]) & ~3u) | (unsigned)(sk[k] - 1);
            slist[wid][cnt + __popc(mk[k] & lmlt)] = __uint_as_float(bits);
        }
        cnt += __popc(mk[k]);
    }
    const int Mr = (int)((cnt + 31u) & ~31u);          // <= 128
    if ((int)cnt + lane < Mr)
        slist[wid][cnt + lane] = RC;                   // sentinel: fc(RC) ~ 5e-8
    __syncwarp();

    // ---- Pass 2: accumulate this half-row ----
    const float sbase = fmaf(2.15f, (float)(lane & 1), 0.9f);
    unsigned long long acc2[16];
    if (Mr == 0) {                                     // warp-uniform (rare)
#pragma unroll
        for (int m = 0; m < 16; ++m) acc2[m] = 0ull;
    } else {
        do_chunk<true>(acc2, slist[wid], 0, lane, sbase);
        for (int base = 32; base < Mr; base += 32)
            do_chunk<false>(acc2, slist[wid], base, lane, sbase);
    }

    // ---- per-warp transpose reduction: lane L -> flats 2L, 2L+1 ----
#pragma unroll
    for (int m = 0; m < 16; ++m) trb[wid][lane][m] = acc2[m];
    __syncwarp();

    const int s_o  = lane >> 3;
    const int p0   = (2 * lane) & 15;
    const int hout = p0 >> 3;
    const int slot = s_o * 4 + ((p0 & 7) >> 1);
    unsigned long long sum = 0ull;
#pragma unroll
    for (int t = 0; t < 16; ++t) {
        const int k = (((t + lane) & 15) << 1) | hout;
        sum = add2(sum, trb[wid][k][slot]);
    }
    psum[wid][lane] = sum;

    // ---- combine warp pair, write output ----
    __syncthreads();
    if (hw == 0) {
        const unsigned long long tot = add2(sum, psum[wid + 1][lane]);
        float2 v;
        v.x = __int_as_float((int)(tot & 0xffffffffull));
        v.y = __int_as_float((int)(tot >> 32));
        reinterpret_cast<float2*>(out)[(size_t)row * 32 + lane] = v;
    }
}

extern "C" void kernel_launch(void* const* d_in, const int* in_sizes, int n_in,
                              void* d_out, int out_size)
{
    const float* dmat;
    const int*   spec;
    int sz_d, sz_s;
    if (in_sizes[0] > in_sizes[1]) {
        dmat = (const float*)d_in[0]; spec = (const int*)d_in[1];
        sz_d = in_sizes[0]; sz_s = in_sizes[1];
    } else {
        dmat = (const float*)d_in[1]; spec = (const int*)d_in[0];
        sz_d = in_sizes[1]; sz_s = in_sizes[0];
    }
    const int N    = sz_d / sz_s;   // 256
    const int rows = sz_s;          // B*N = 16384

    dim3 grid(rows / 2);            // 2 rows per block (2 warps per row)
    dim3 block(128);
    radial_aev_kernel<<<grid, block>>>(dmat, spec, (float*)d_out, N);
}

// round 16
// speedup vs baseline: 1.2521x; 1.2521x over previous
#include <cuda_runtime.h>
#include <cstdint>

// RadialAEVComputer: GR[b,i,s,p] = sum_j exp(-16*(d_bij - shf_p)^2) * fc(d_bij) * [spec_bj == s+1]
// B=64, N=256, S=4, P=16, shf_p = 0.9 + 0.26875*p, RC=5.2
//
// R16 (final): R14 core + two-chain final reduction.
//   Pass 1: float4/int4 loads, 8 independent ballots, register prefix,
//           packed (d | species) smem list, sentinel d = RC.
//   Pass 2: lane-pair p-split; LDS.64 pair-loads; odd-from-even Gaussians
//           (5 ex2/neighbor); peeled mul-init; packed weight selects.
//   Reduce: smem transpose, two independent add2 chains.

#define WPB 4
#define FULL 0xffffffffu

__device__ __forceinline__ unsigned long long pack2(float lo, float hi) {
    unsigned long long r;
    asm("mov.b64 %0, {%1, %2};" : "=l"(r) : "f"(lo), "f"(hi));
    return r;
}
__device__ __forceinline__ void fma2_acc(unsigned long long& d,
                                         unsigned long long a,
                                         unsigned long long b) {
    asm("fma.rn.f32x2 %0, %1, %2, %0;" : "+l"(d) : "l"(a), "l"(b));
}
__device__ __forceinline__ unsigned long long mul2(unsigned long long a,
                                                   unsigned long long b) {
    unsigned long long r;
    asm("mul.rn.f32x2 %0, %1, %2;" : "=l"(r) : "l"(a), "l"(b));
    return r;
}
__device__ __forceinline__ unsigned long long add2(unsigned long long a,
                                                   unsigned long long b) {
    unsigned long long r;
    asm("add.rn.f32x2 %0, %1, %2;" : "=l"(r) : "l"(a), "l"(b));
    return r;
}
__device__ __forceinline__ float ex2f(float a) {
    float t;
    asm("ex2.approx.ftz.f32 %0, %1;" : "=f"(t) : "f"(a));
    return t;
}

// delta = 0.26875, NL = -16*log2(e) = -23.0831207
//   R0 arg:  NL*delta*(delta - 2*dh) = 12.4071774*dh - 1.6672145
//   CR = 9.8282033e-3;  CR^2 = 9.6593541e-5;  CR^3 = 9.4934069e-7

template <bool FIRST>
__device__ __forceinline__ void do_chunk(unsigned long long (&acc2)[16],
                                         const float* __restrict__ sl,
                                         int base, int lane, float sbase)
{
    const float NL    = -23.0831207f;
    const float PI_RC = 0.60415244f;

    // lanes 2k, 2k+1 read the same 8-byte pair: one LDS.64, smem broadcast
    const float2 e = *reinterpret_cast<const float2*>(&sl[base + (lane & ~1)]);
    const unsigned bits0 = __float_as_uint(e.x);
    const unsigned bits1 = __float_as_uint(e.y);
    const float d0 = e.x, d1 = e.y;
    const int c0 = bits0 & 3;
    const int c1 = bits1 & 3;

    const float ws0 = fmaf(0.5f, __cosf(d0 * PI_RC), 0.5f);
    const float ws1 = fmaf(0.5f, __cosf(d1 * PI_RC), 0.5f);

    {   // neighbor 0
        const float dh = d0 - sbase;
        const float t  = dh * NL;
        const float A  = dh * t;
        const float Bv = -2.0f * t;
        const float R0 = ex2f(fmaf(dh, 12.4071774f, -1.6672145f));
        const float R1 = R0 * 9.8282033e-3f;
        const float R2 = R0 * 9.6593541e-5f;
        const float R3 = R0 * 9.4934069e-7f;
        const unsigned long long wwp = pack2(ws0, ws0);
        const unsigned long long ww0 = (c0 == 0) ? wwp : 0ull;
        const unsigned long long ww1 = (c0 == 1) ? wwp : 0ull;
        const unsigned long long ww2 = (c0 == 2) ? wwp : 0ull;
        const unsigned long long ww3 = (c0 == 3) ? wwp : 0ull;
#pragma unroll
        for (int u = 0; u < 4; ++u) {
            const float q  = 0.26875f * (float)(2 * u);
            const float g  = ex2f(fmaf(Bv, q, A) + NL * q * q);
            const float Ru = (u == 0) ? R0 : (u == 1) ? R1 : (u == 2) ? R2 : R3;
            const unsigned long long tt = pack2(g, g * Ru);
            if (FIRST) {
                acc2[u]      = mul2(tt, ww0);
                acc2[4 + u]  = mul2(tt, ww1);
                acc2[8 + u]  = mul2(tt, ww2);
                acc2[12 + u] = mul2(tt, ww3);
            } else {
                fma2_acc(acc2[u],      tt, ww0);
                fma2_acc(acc2[4 + u],  tt, ww1);
                fma2_acc(acc2[8 + u],  tt, ww2);
                fma2_acc(acc2[12 + u], tt, ww3);
            }
        }
    }
    {   // neighbor 1
        const float dh = d1 - sbase;
        const float t  = dh * NL;
        const float A  = dh * t;
        const float Bv = -2.0f * t;
        const float R0 = ex2f(fmaf(dh, 12.4071774f, -1.6672145f));
        const float R1 = R0 * 9.8282033e-3f;
        const float R2 = R0 * 9.6593541e-5f;
        const float R3 = R0 * 9.4934069e-7f;
        const unsigned long long wwp = pack2(ws1, ws1);
        const unsigned long long ww0 = (c1 == 0) ? wwp : 0ull;
        const unsigned long long ww1 = (c1 == 1) ? wwp : 0ull;
        const unsigned long long ww2 = (c1 == 2) ? wwp : 0ull;
        const unsigned long long ww3 = (c1 == 3) ? wwp : 0ull;
#pragma unroll
        for (int u = 0; u < 4; ++u) {
            const float q  = 0.26875f * (float)(2 * u);
            const float g  = ex2f(fmaf(Bv, q, A) + NL * q * q);
            const float Ru = (u == 0) ? R0 : (u == 1) ? R1 : (u == 2) ? R2 : R3;
            const unsigned long long tt = pack2(g, g * Ru);
            fma2_acc(acc2[u],      tt, ww0);
            fma2_acc(acc2[4 + u],  tt, ww1);
            fma2_acc(acc2[8 + u],  tt, ww2);
            fma2_acc(acc2[12 + u], tt, ww3);
        }
    }
}

__global__ __launch_bounds__(32 * WPB, 8)
void radial_aev_kernel(const float* __restrict__ dmat,
                       const int*   __restrict__ spec,
                       float*       __restrict__ out,
                       int N)
{
    __shared__ float slist[WPB][256];
    __shared__ unsigned long long trb[WPB][32][17];   // padded vs bank conflicts

    const int lane = threadIdx.x & 31;
    const int wid  = threadIdx.x >> 5;
    const int row  = blockIdx.x * WPB + wid;          // b*N + i
    const int b    = row >> 8;                        // N == 256

    const float RC = 5.2f;
    const unsigned lmlt = (1u << lane) - 1u;

    // ---- Pass 1: batched ballots (independent), register prefix, stores ----
    const float4* __restrict__ drow4 = (const float4*)(dmat + (size_t)row * N);
    const int4*   __restrict__ srow4 = (const int4*)(spec + b * N);

    const float4 dv0 = drow4[lane];
    const float4 dv1 = drow4[32 + lane];
    const int4   sv0 = srow4[lane];
    const int4   sv1 = srow4[32 + lane];

    const float dk[8] = { dv0.x, dv0.y, dv0.z, dv0.w, dv1.x, dv1.y, dv1.z, dv1.w };
    const int   sk[8] = { sv0.x, sv0.y, sv0.z, sv0.w, sv1.x, sv1.y, sv1.z, sv1.w };

    unsigned mk[8];
#pragma unroll
    for (int k = 0; k < 8; ++k)                        // independent ballots
        mk[k] = __ballot_sync(FULL, (dk[k] < RC) && (dk[k] != 0.0f));

    unsigned cnt = 0;
#pragma unroll
    for (int k = 0; k < 8; ++k) {
        if ((mk[k] >> lane) & 1u) {
            const unsigned bits = (__float_as_uint(dk[k]) & ~3u) | (unsigned)(sk[k] - 1);
            slist[wid][cnt + __popc(mk[k] & lmlt)] = __uint_as_float(bits);
        }
        cnt += __popc(mk[k]);
    }
    const int Mr = (int)((cnt + 31u) & ~31u);

    if (Mr == 0) {                                    // warp-uniform
        reinterpret_cast<float2*>(out)[(size_t)row * 32 + lane] = make_float2(0.0f, 0.0f);
        return;
    }
    if ((int)cnt + lane < Mr)
        slist[wid][cnt + lane] = RC;     // sentinel: fc(RC) ~ 5e-8, Gaussian ~ 0
    __syncwarp();

    // ---- Pass 2: compacted accumulation, lane-pair p-split ----
    const float sbase = fmaf(2.15f, (float)(lane & 1), 0.9f);

    unsigned long long acc2[16];
    do_chunk<true>(acc2, slist[wid], 0, lane, sbase);
    for (int base = 32; base < Mr; base += 32)
        do_chunk<false>(acc2, slist[wid], base, lane, sbase);

    // ---- Reduction via smem transpose (two independent add2 chains) ----
#pragma unroll
    for (int m = 0; m < 16; ++m) trb[wid][lane][m] = acc2[m];
    __syncwarp();

    const int s_o  = lane >> 3;
    const int p0   = (2 * lane) & 15;
    const int hout = p0 >> 3;
    const int slot = s_o * 4 + ((p0 & 7) >> 1);
    unsigned long long sumA = 0ull, sumB = 0ull;
#pragma unroll
    for (int t = 0; t < 16; t += 2) {
        const int kA = (((t + lane) & 15) << 1) | hout;       // staggered
        const int kB = (((t + 1 + lane) & 15) << 1) | hout;
        sumA = add2(sumA, trb[wid][kA][slot]);
        sumB = add2(sumB, trb[wid][kB][slot]);
    }
    const unsigned long long sum = add2(sumA, sumB);

    float2 v;
    v.x = __int_as_float((int)(sum & 0xffffffffull));
    v.y = __int_as_float((int)(sum >> 32));
    reinterpret_cast<float2*>(out)[(size_t)row * 32 + lane] = v;
}

extern "C" void kernel_launch(void* const* d_in, const int* in_sizes, int n_in,
                              void* d_out, int out_size)
{
    const float* dmat;
    const int*   spec;
    int sz_d, sz_s;
    if (in_sizes[0] > in_sizes[1]) {
        dmat = (const float*)d_in[0]; spec = (const int*)d_in[1];
        sz_d = in_sizes[0]; sz_s = in_sizes[1];
    } else {
        dmat = (const float*)d_in[1]; spec = (const int*)d_in[0];
        sz_d = in_sizes[1]; sz_s = in_sizes[0];
    }
    const int N    = sz_d / sz_s;   // 256
    const int rows = sz_s;          // B*N = 16384

    dim3 grid(rows / WPB);
    dim3 block(32 * WPB);
    radial_aev_kernel<<<grid, block>>>(dmat, spec, (float*)d_out, N);
}

// round 17
// speedup vs baseline: 1.2737x; 1.0172x over previous
#include <cuda_runtime.h>
#include <cstdint>

// RadialAEVComputer: GR[b,i,s,p] = sum_j exp(-16*(d_bij - shf_p)^2) * fc(d_bij) * [spec_bj == s+1]
// B=64, N=256, S=4, P=16, shf_p = 0.9 + 0.26875*p, RC=5.2
//
// FINAL (R14 config, best measured: ncu 13.34 us, bench 14.85 us):
//   Pass 1: float4/int4 loads, 8 independent ballots, register prefix,
//           packed (d | species-in-2-LSBs) smem list, sentinel d = RC.
//   Pass 2: lane-pair p-split (lane parity owns 8 of 16 shifts); LDS.64
//           pair-loads (smem broadcast, no SHFLs); odd-from-even Gaussians
//           (5 ex2 per neighbor via ratio powers); peeled mul-init (no
//           accumulator zero-fill); packed f32x2 scatter with 64-bit
//           weight selects.
//   Reduce: staggered smem transpose (16 STS.64 + 16 LDS.64 + 16 add2),
//           coalesced float2 stores.

#define WPB 4
#define FULL 0xffffffffu

__device__ __forceinline__ unsigned long long pack2(float lo, float hi) {
    unsigned long long r;
    asm("mov.b64 %0, {%1, %2};" : "=l"(r) : "f"(lo), "f"(hi));
    return r;
}
__device__ __forceinline__ void fma2_acc(unsigned long long& d,
                                         unsigned long long a,
                                         unsigned long long b) {
    asm("fma.rn.f32x2 %0, %1, %2, %0;" : "+l"(d) : "l"(a), "l"(b));
}
__device__ __forceinline__ unsigned long long mul2(unsigned long long a,
                                                   unsigned long long b) {
    unsigned long long r;
    asm("mul.rn.f32x2 %0, %1, %2;" : "=l"(r) : "l"(a), "l"(b));
    return r;
}
__device__ __forceinline__ unsigned long long add2(unsigned long long a,
                                                   unsigned long long b) {
    unsigned long long r;
    asm("add.rn.f32x2 %0, %1, %2;" : "=l"(r) : "l"(a), "l"(b));
    return r;
}
__device__ __forceinline__ float ex2f(float a) {
    float t;
    asm("ex2.approx.ftz.f32 %0, %1;" : "=f"(t) : "f"(a));
    return t;
}

// delta = 0.26875, NL = -16*log2(e) = -23.0831207
//   R0 arg:  NL*delta*(delta - 2*dh) = 12.4071774*dh - 1.6672145
//   CR = 9.8282033e-3;  CR^2 = 9.6593541e-5;  CR^3 = 9.4934069e-7

template <bool FIRST>
__device__ __forceinline__ void do_chunk(unsigned long long (&acc2)[16],
                                         const float* __restrict__ sl,
                                         int base, int lane, float sbase)
{
    const float NL    = -23.0831207f;
    const float PI_RC = 0.60415244f;

    // lanes 2k, 2k+1 read the same 8-byte pair: one LDS.64, smem broadcast
    const float2 e = *reinterpret_cast<const float2*>(&sl[base + (lane & ~1)]);
    const unsigned bits0 = __float_as_uint(e.x);
    const unsigned bits1 = __float_as_uint(e.y);
    const float d0 = e.x, d1 = e.y;
    const int c0 = bits0 & 3;
    const int c1 = bits1 & 3;

    const float ws0 = fmaf(0.5f, __cosf(d0 * PI_RC), 0.5f);
    const float ws1 = fmaf(0.5f, __cosf(d1 * PI_RC), 0.5f);

    {   // neighbor 0
        const float dh = d0 - sbase;
        const float t  = dh * NL;
        const float A  = dh * t;
        const float Bv = -2.0f * t;
        const float R0 = ex2f(fmaf(dh, 12.4071774f, -1.6672145f));
        const float R1 = R0 * 9.8282033e-3f;
        const float R2 = R0 * 9.6593541e-5f;
        const float R3 = R0 * 9.4934069e-7f;
        const unsigned long long wwp = pack2(ws0, ws0);
        const unsigned long long ww0 = (c0 == 0) ? wwp : 0ull;
        const unsigned long long ww1 = (c0 == 1) ? wwp : 0ull;
        const unsigned long long ww2 = (c0 == 2) ? wwp : 0ull;
        const unsigned long long ww3 = (c0 == 3) ? wwp : 0ull;
#pragma unroll
        for (int u = 0; u < 4; ++u) {
            const float q  = 0.26875f * (float)(2 * u);
            const float g  = ex2f(fmaf(Bv, q, A) + NL * q * q);
            const float Ru = (u == 0) ? R0 : (u == 1) ? R1 : (u == 2) ? R2 : R3;
            const unsigned long long tt = pack2(g, g * Ru);
            if (FIRST) {
                acc2[u]      = mul2(tt, ww0);
                acc2[4 + u]  = mul2(tt, ww1);
                acc2[8 + u]  = mul2(tt, ww2);
                acc2[12 + u] = mul2(tt, ww3);
            } else {
                fma2_acc(acc2[u],      tt, ww0);
                fma2_acc(acc2[4 + u],  tt, ww1);
                fma2_acc(acc2[8 + u],  tt, ww2);
                fma2_acc(acc2[12 + u], tt, ww3);
            }
        }
    }
    {   // neighbor 1
        const float dh = d1 - sbase;
        const float t  = dh * NL;
        const float A  = dh * t;
        const float Bv = -2.0f * t;
        const float R0 = ex2f(fmaf(dh, 12.4071774f, -1.6672145f));
        const float R1 = R0 * 9.8282033e-3f;
        const float R2 = R0 * 9.6593541e-5f;
        const float R3 = R0 * 9.4934069e-7f;
        const unsigned long long wwp = pack2(ws1, ws1);
        const unsigned long long ww0 = (c1 == 0) ? wwp : 0ull;
        const unsigned long long ww1 = (c1 == 1) ? wwp : 0ull;
        const unsigned long long ww2 = (c1 == 2) ? wwp : 0ull;
        const unsigned long long ww3 = (c1 == 3) ? wwp : 0ull;
#pragma unroll
        for (int u = 0; u < 4; ++u) {
            const float q  = 0.26875f * (float)(2 * u);
            const float g  = ex2f(fmaf(Bv, q, A) + NL * q * q);
            const float Ru = (u == 0) ? R0 : (u == 1) ? R1 : (u == 2) ? R2 : R3;
            const unsigned long long tt = pack2(g, g * Ru);
            fma2_acc(acc2[u],      tt, ww0);
            fma2_acc(acc2[4 + u],  tt, ww1);
            fma2_acc(acc2[8 + u],  tt, ww2);
            fma2_acc(acc2[12 + u], tt, ww3);
        }
    }
}

__global__ __launch_bounds__(32 * WPB, 8)
void radial_aev_kernel(const float* __restrict__ dmat,
                       const int*   __restrict__ spec,
                       float*       __restrict__ out,
                       int N)
{
    __shared__ float slist[WPB][256];
    __shared__ unsigned long long trb[WPB][32][17];   // padded vs bank conflicts

    const int lane = threadIdx.x & 31;
    const int wid  = threadIdx.x >> 5;
    const int row  = blockIdx.x * WPB + wid;          // b*N + i
    const int b    = row >> 8;                        // N == 256

    const float RC = 5.2f;
    const unsigned lmlt = (1u << lane) - 1u;

    // ---- Pass 1: batched ballots (independent), register prefix, stores ----
    const float4* __restrict__ drow4 = (const float4*)(dmat + (size_t)row * N);
    const int4*   __restrict__ srow4 = (const int4*)(spec + b * N);

    const float4 dv0 = drow4[lane];
    const float4 dv1 = drow4[32 + lane];
    const int4   sv0 = srow4[lane];
    const int4   sv1 = srow4[32 + lane];

    const float dk[8] = { dv0.x, dv0.y, dv0.z, dv0.w, dv1.x, dv1.y, dv1.z, dv1.w };
    const int   sk[8] = { sv0.x, sv0.y, sv0.z, sv0.w, sv1.x, sv1.y, sv1.z, sv1.w };

    unsigned mk[8];
#pragma unroll
    for (int k = 0; k < 8; ++k)                        // independent ballots
        mk[k] = __ballot_sync(FULL, (dk[k] < RC) && (dk[k] != 0.0f));

    unsigned cnt = 0;
#pragma unroll
    for (int k = 0; k < 8; ++k) {
        if ((mk[k] >> lane) & 1u) {
            const unsigned bits = (__float_as_uint(dk[k]) & ~3u) | (unsigned)(sk[k] - 1);
            slist[wid][cnt + __popc(mk[k] & lmlt)] = __uint_as_float(bits);
        }
        cnt += __popc(mk[k]);
    }
    const int Mr = (int)((cnt + 31u) & ~31u);

    if (Mr == 0) {                                    // warp-uniform
        reinterpret_cast<float2*>(out)[(size_t)row * 32 + lane] = make_float2(0.0f, 0.0f);
        return;
    }
    if ((int)cnt + lane < Mr)
        slist[wid][cnt + lane] = RC;     // sentinel: fc(RC) ~ 5e-8, Gaussian ~ 0
    __syncwarp();

    // ---- Pass 2: compacted accumulation, lane-pair p-split ----
    const float sbase = fmaf(2.15f, (float)(lane & 1), 0.9f);

    unsigned long long acc2[16];
    do_chunk<true>(acc2, slist[wid], 0, lane, sbase);
    for (int base = 32; base < Mr; base += 32)
        do_chunk<false>(acc2, slist[wid], base, lane, sbase);

    // ---- Reduction via smem transpose ----
#pragma unroll
    for (int m = 0; m < 16; ++m) trb[wid][lane][m] = acc2[m];
    __syncwarp();

    const int s_o  = lane >> 3;
    const int p0   = (2 * lane) & 15;
    const int hout = p0 >> 3;
    const int slot = s_o * 4 + ((p0 & 7) >> 1);
    unsigned long long sum = 0ull;
#pragma unroll
    for (int t = 0; t < 16; ++t) {
        const int k = (((t + lane) & 15) << 1) | hout;   // staggered, parity hout
        sum = add2(sum, trb[wid][k][slot]);
    }

    float2 v;
    v.x = __int_as_float((int)(sum & 0xffffffffull));
    v.y = __int_as_float((int)(sum >> 32));
    reinterpret_cast<float2*>(out)[(size_t)row * 32 + lane] = v;
}

extern "C" void kernel_launch(void* const* d_in, const int* in_sizes, int n_in,
                              void* d_out, int out_size)
{
    const float* dmat;
    const int*   spec;
    int sz_d, sz_s;
    if (in_sizes[0] > in_sizes[1]) {
        dmat = (const float*)d_in[0]; spec = (const int*)d_in[1];
        sz_d = in_sizes[0]; sz_s = in_sizes[1];
    } else {
        dmat = (const float*)d_in[1]; spec = (const int*)d_in[0];
        sz_d = in_sizes[1]; sz_s = in_sizes[0];
    }
    const int N    = sz_d / sz_s;   // 256
    const int rows = sz_s;          // B*N = 16384

    dim3 grid(rows / WPB);
    dim3 block(32 * WPB);
    radial_aev_kernel<<<grid, block>>>(dmat, spec, (float*)d_out, N);
}